// round 14
// baseline (speedup 1.0000x reference)
#include <cuda_runtime.h>
#include <cuda_fp16.h>
#include <cstdint>

#define NN 20000
#define NE 320000
#define NB 32
#define HDIM 64
#define HC 256   // H*C
#define NH 4
#define NL 3

// ---------------- scratch (device globals; no allocation allowed) ----------
__device__ int    g_deg[NN];
__device__ int    g_rowptr[NN + 1];
__device__ int    g_fill[NN];
__device__ int    g_csrc[NE];
__device__ __half g_hh[NN * HDIM];         // fp16 node features (layer input)
__device__ __half g_Wh[NL * HDIM * HC];    // fp16 conv weights
__device__ __half g_xph[NN * HC];          // fp16 projected features
__device__ float  g_as[NN * NH];
__device__ float  g_ad[NN * NH];
__device__ float  g_aedeP[NL * NE * 4];    // per-layer planes of edge logits, CSR order
__device__ float  g_weatt[HDIM * 12];
__device__ float  g_pool[NB * HDIM];
__device__ int    g_cnt[NB];

__device__ __forceinline__ float lrelu(float x) { return x > 0.f ? x : 0.2f * x; }

// ---------------- combined pre-kernel ---------------------------------------
#define PRE_WEATT_BLOCKS 96
__global__ __launch_bounds__(256) void pre_kernel(const int* __restrict__ dst,
                                                  const float* __restrict__ x,
                                                  const float* __restrict__ node_W,
                                                  const float* __restrict__ node_b,
                                                  const float* __restrict__ lin_eW,
                                                  const float* __restrict__ att_e,
                                                  const float* __restrict__ lin_W) {
    if (blockIdx.x < PRE_WEATT_BLOCKS) {
        int wid = (blockIdx.x * 256 + threadIdx.x) >> 5;
        int lane = threadIdx.x & 31;
        if (wid >= NL * HDIM * NH) return;
        int l = wid >> 8;
        int rem = wid & 255;
        int d = rem >> 2;
        int h = rem & 3;
        const float* w = lin_eW + l * HDIM * HC + d * HC + h * 64;
        const float* a = att_e + l * NH * 64 + h * 64;
        float s = w[lane] * a[lane] + w[32 + lane] * a[32 + lane];
        #pragma unroll
        for (int off = 16; off >= 1; off >>= 1) s += __shfl_xor_sync(0xffffffffu, s, off);
        if (lane == 0) g_weatt[d * 12 + l * 4 + h] = s;
        return;
    }
    int idx = (blockIdx.x - PRE_WEATT_BLOCKS) * 256 + threadIdx.x;
    if (idx < NE) atomicAdd(&g_deg[dst[idx]], 1);
    if (idx < NB * HDIM) g_pool[idx] = 0.f;
    if (idx < NB) g_cnt[idx] = 0;
    if (idx < NL * HDIM * HC / 2) {
        float2 wv = *(const float2*)&lin_W[idx * 2];
        *(__half2*)&g_Wh[idx * 2] = __floats2half2_rn(wv.x, wv.y);
    }
    if (idx < NN * HDIM) {
        int n = idx >> 6, c = idx & 63;
        float v = x[n * 3 + 0] * node_W[c] + x[n * 3 + 1] * node_W[64 + c]
                + x[n * 3 + 2] * node_W[128 + c] + node_b[c];
        g_hh[idx] = __float2half(fmaxf(v, 0.f));
    }
}

// ---------------- scan: single block, 20 elements per thread ---------------
__global__ __launch_bounds__(1024) void scan_kernel() {
    __shared__ int wsum[32];
    const int PER = 20;
    int t = threadIdx.x;
    int lane = t & 31, w = t >> 5;
    int v[PER];
    int sum = 0;
    int base = t * PER;
    if (t < 1000) {
        #pragma unroll
        for (int i = 0; i < PER; i++) {
            sum += g_deg[base + i];
            v[i] = sum;
        }
    }
    int x = sum;
    #pragma unroll
    for (int off = 1; off < 32; off <<= 1) {
        int y = __shfl_up_sync(0xffffffffu, x, off);
        if (lane >= off) x += y;
    }
    if (lane == 31) wsum[w] = x;
    __syncthreads();
    if (w == 0) {
        int y = wsum[lane];
        #pragma unroll
        for (int off = 1; off < 32; off <<= 1) {
            int z = __shfl_up_sync(0xffffffffu, y, off);
            if (lane >= off) y += z;
        }
        wsum[lane] = y;
    }
    __syncthreads();
    int prefix = x - sum + (w > 0 ? wsum[w - 1] : 0);
    if (t < 1000) {
        if (t == 0) g_rowptr[0] = 0;
        #pragma unroll
        for (int i = 0; i < PER; i++) g_rowptr[base + i + 1] = prefix + v[i];
    }
}

// ---- edge embedding -> 12 logits, fused CSR scatter (no atomics to aeds) ----
__global__ __launch_bounds__(256) void edge_emb_kernel(const float* __restrict__ eattr,
                                                       const int* __restrict__ src,
                                                       const int* __restrict__ dst,
                                                       const float* __restrict__ eemb_W,
                                                       const float* __restrict__ eemb_b) {
    __shared__ float4 sW4[64];
    __shared__ float  sb64[64];
    __shared__ float4 sA4[64 * 3];
    int t = threadIdx.x;
    if (t < 64) {
        sW4[t] = make_float4(eemb_W[t], eemb_W[64 + t], eemb_W[128 + t], eemb_W[192 + t]);
        sb64[t] = eemb_b[t];
    }
    for (int i = t; i < 64 * 3; i += 256) sA4[i] = ((const float4*)g_weatt)[i];
    __syncthreads();

    int e = blockIdx.x * blockDim.x + t;
    if (e >= NE) return;
    float4 a = *(const float4*)&eattr[e * 4];
    float aed[12];
    #pragma unroll
    for (int o = 0; o < 12; o++) aed[o] = 0.f;
    #pragma unroll 4
    for (int d = 0; d < 64; d++) {
        float4 w = sW4[d];
        float ea = fmaxf(a.x * w.x + a.y * w.y + a.z * w.z + a.w * w.w + sb64[d], 0.f);
        float4 A0 = sA4[d * 3 + 0], A1 = sA4[d * 3 + 1], A2 = sA4[d * 3 + 2];
        aed[0] += ea * A0.x; aed[1] += ea * A0.y; aed[2]  += ea * A0.z; aed[3]  += ea * A0.w;
        aed[4] += ea * A1.x; aed[5] += ea * A1.y; aed[6]  += ea * A1.z; aed[7]  += ea * A1.w;
        aed[8] += ea * A2.x; aed[9] += ea * A2.y; aed[10] += ea * A2.z; aed[11] += ea * A2.w;
    }
    int dn = dst[e];
    int sn = src[e];
    int p = atomicAdd(&g_fill[dn], 1);
    int slot = g_rowptr[dn] + p;
    g_csrc[slot] = sn;
    float4* P = (float4*)g_aedeP;
    P[0 * NE + slot] = make_float4(aed[0], aed[1], aed[2],  aed[3]);
    P[1 * NE + slot] = make_float4(aed[4], aed[5], aed[6],  aed[7]);
    P[2 * NE + slot] = make_float4(aed[8], aed[9], aed[10], aed[11]);
}

// ---------------- tensor-core GEMM + fused a_s/a_d --------------------------
// 32 rows x 256 cols per block, 8 warps; warp = (wm 0..1)+2*wn: 16 rows x 64 cols
// (warp column range == one head). 625 blocks exactly (20000/32) -> no guards.
__device__ __forceinline__ void mma16816(float& c0, float& c1, float& c2, float& c3,
                                         uint32_t a0, uint32_t a1, uint32_t a2, uint32_t a3,
                                         uint32_t b0, uint32_t b1) {
    asm volatile(
        "mma.sync.aligned.m16n8k16.row.col.f32.f16.f16.f32 "
        "{%0,%1,%2,%3},{%4,%5,%6,%7},{%8,%9},{%0,%1,%2,%3};"
        : "+f"(c0), "+f"(c1), "+f"(c2), "+f"(c3)
        : "r"(a0), "r"(a1), "r"(a2), "r"(a3), "r"(b0), "r"(b1));
}

#define BPAD 264   // 256 + 8 halves

__global__ __launch_bounds__(256) void gemm_attn_kernel(int layer,
                                                        const float* __restrict__ att_src,
                                                        const float* __restrict__ att_dst) {
    __shared__ __half Ah[32][72];
    __shared__ __half Bh[64][BPAD];
    __shared__ float  sAs[256], sAd[256];

    int tid = threadIdx.x;
    int warp = tid >> 5, lane = tid & 31;
    int n0 = blockIdx.x * 32;

    sAs[tid] = att_src[tid];
    sAd[tid] = att_dst[tid];

    // load A (fp16 h): thread -> row tid>>3 (0..31), 8 halves at (tid&7)*8
    {
        int row = tid >> 3, cb = (tid & 7) * 8;
        *(uint4*)&Ah[row][cb] = *(const uint4*)&g_hh[(size_t)(n0 + row) * HDIM + cb];
    }
    // load W (fp16): thread -> k row tid>>2 (0..63), 64 halves at (tid&3)*64
    {
        int kr = tid >> 2, cb = (tid & 3) * 64;
        const uint4* srcp = (const uint4*)&g_Wh[(size_t)layer * HDIM * HC + (size_t)kr * HC + cb];
        uint4* dstp = (uint4*)&Bh[kr][cb];
        #pragma unroll
        for (int i = 0; i < 8; i++) dstp[i] = srcp[i];
    }
    __syncthreads();

    int wm = warp & 1, wn = warp >> 1;        // wn = head
    int mrow = wm * 16;
    int ncol0 = wn * 64;

    uint32_t afr[4][4];
    {
        int r = mrow + (lane & 7) + ((lane >> 3) & 1) * 8;
        int kc = ((lane >> 4) & 1) * 8;
        #pragma unroll
        for (int ks = 0; ks < 4; ks++) {
            unsigned addr = (unsigned)__cvta_generic_to_shared(&Ah[r][ks * 16 + kc]);
            asm volatile("ldmatrix.sync.aligned.m8n8.x4.shared.b16 {%0,%1,%2,%3}, [%4];"
                         : "=r"(afr[ks][0]), "=r"(afr[ks][1]), "=r"(afr[ks][2]), "=r"(afr[ks][3])
                         : "r"(addr));
        }
    }

    float acc[8][4];
    #pragma unroll
    for (int nt = 0; nt < 8; nt++)
        #pragma unroll
        for (int j = 0; j < 4; j++) acc[nt][j] = 0.f;

    int bl8 = lane & 7, bm2 = (lane >> 3) & 1;
    #pragma unroll
    for (int nt = 0; nt < 8; nt++) {
        int ncol = ncol0 + nt * 8;
        #pragma unroll
        for (int ks = 0; ks < 4; ks++) {
            unsigned addr = (unsigned)__cvta_generic_to_shared(&Bh[ks * 16 + bl8 + bm2 * 8][ncol]);
            uint32_t b0, b1;
            asm volatile("ldmatrix.sync.aligned.m8n8.x2.trans.shared.b16 {%0,%1}, [%2];"
                         : "=r"(b0), "=r"(b1) : "r"(addr));
            mma16816(acc[nt][0], acc[nt][1], acc[nt][2], acc[nt][3],
                     afr[ks][0], afr[ks][1], afr[ks][2], afr[ks][3], b0, b1);
        }
    }

    // a_s/a_d from fragments (warp cols == head wn)
    {
        int c0 = ncol0 + (lane & 3) * 2;
        int row0 = mrow + (lane >> 2);
        float sp0 = 0.f, sp1 = 0.f, dp0 = 0.f, dp1 = 0.f;
        #pragma unroll
        for (int nt = 0; nt < 8; nt++) {
            float a0 = sAs[c0 + nt * 8], a1 = sAs[c0 + nt * 8 + 1];
            float d0 = sAd[c0 + nt * 8], d1 = sAd[c0 + nt * 8 + 1];
            sp0 += acc[nt][0] * a0 + acc[nt][1] * a1;
            sp1 += acc[nt][2] * a0 + acc[nt][3] * a1;
            dp0 += acc[nt][0] * d0 + acc[nt][1] * d1;
            dp1 += acc[nt][2] * d0 + acc[nt][3] * d1;
        }
        #pragma unroll
        for (int off = 1; off <= 2; off <<= 1) {
            sp0 += __shfl_xor_sync(0xffffffffu, sp0, off);
            sp1 += __shfl_xor_sync(0xffffffffu, sp1, off);
            dp0 += __shfl_xor_sync(0xffffffffu, dp0, off);
            dp1 += __shfl_xor_sync(0xffffffffu, dp1, off);
        }
        if ((lane & 3) == 0) {
            g_as[(n0 + row0) * 4 + wn] = sp0;
            g_ad[(n0 + row0) * 4 + wn] = dp0;
            g_as[(n0 + row0 + 8) * 4 + wn] = sp1;
            g_ad[(n0 + row0 + 8) * 4 + wn] = dp1;
        }
    }

    // direct xp stores from fragments
    {
        int r0g = n0 + mrow + (lane >> 2);
        int c0 = ncol0 + (lane & 3) * 2;
        #pragma unroll
        for (int nt = 0; nt < 8; nt++) {
            *(__half2*)&g_xph[(size_t)r0g * HC + c0 + nt * 8] =
                __floats2half2_rn(acc[nt][0], acc[nt][1]);
            *(__half2*)&g_xph[(size_t)(r0g + 8) * HC + c0 + nt * 8] =
                __floats2half2_rn(acc[nt][2], acc[nt][3]);
        }
    }
}

// ---- softmax + aggregation, 1 warp/node (R9 structure; self-logit fused) ---
__global__ __launch_bounds__(256) void aggr_kernel(const float* __restrict__ conv_b, int layer,
                                                   const int* __restrict__ batch) {
    int warp = (blockIdx.x * blockDim.x + threadIdx.x) >> 5;
    if (warp >= NN) return;
    int lane = threadIdx.x & 31;
    int n = warp;
    int beg = g_rowptr[n], end = g_rowptr[n + 1];

    float4 adv = *(const float4*)&g_ad[n * 4];
    float4 asl = *(const float4*)&g_as[n * 4];

    float den0 = 0.f, den1 = 0.f, den2 = 0.f, den3 = 0.f;
    float sae0 = 0.f, sae1 = 0.f, sae2 = 0.f, sae3 = 0.f;  // sum of edge logits
    float acc[8];
    #pragma unroll
    for (int j = 0; j < 8; j++) acc[j] = 0.f;

    const float4* plane = (const float4*)g_aedeP + (size_t)layer * NE;
    for (int base = beg; base < end; base += 32) {
        int cnt = min(32, end - base);
        float f0 = 0.f, f1 = 0.f, f2 = 0.f, f3 = 0.f;
        int ss = 0;
        if (lane < cnt) {
            int e = base + lane;
            ss = g_csrc[e];
            float4 av = *(const float4*)&g_as[ss * 4];
            float4 ae = plane[e];
            sae0 += ae.x; sae1 += ae.y; sae2 += ae.z; sae3 += ae.w;
            f0 = __expf(lrelu(av.x + adv.x + ae.x));
            f1 = __expf(lrelu(av.y + adv.y + ae.y));
            f2 = __expf(lrelu(av.z + adv.z + ae.z));
            f3 = __expf(lrelu(av.w + adv.w + ae.w));
        }
        den0 += f0; den1 += f1; den2 += f2; den3 += f3;
        #pragma unroll 2
        for (int t = 0; t < cnt; t++) {
            float b0 = __shfl_sync(0xffffffffu, f0, t);
            float b1 = __shfl_sync(0xffffffffu, f1, t);
            float b2 = __shfl_sync(0xffffffffu, f2, t);
            float b3 = __shfl_sync(0xffffffffu, f3, t);
            int sb = __shfl_sync(0xffffffffu, ss, t);
            const __half2* xr = (const __half2*)(g_xph + (size_t)sb * HC) + lane;
            float2 p0 = __half22float2(xr[0]);
            float2 p1 = __half22float2(xr[32]);
            float2 p2 = __half22float2(xr[64]);
            float2 p3 = __half22float2(xr[96]);
            acc[0] += b0 * p0.x; acc[1] += b0 * p0.y;
            acc[2] += b1 * p1.x; acc[3] += b1 * p1.y;
            acc[4] += b2 * p2.x; acc[5] += b2 * p2.y;
            acc[6] += b3 * p3.x; acc[7] += b3 * p3.y;
        }
    }
    #pragma unroll
    for (int off = 16; off >= 1; off >>= 1) {
        den0 += __shfl_xor_sync(0xffffffffu, den0, off);
        den1 += __shfl_xor_sync(0xffffffffu, den1, off);
        den2 += __shfl_xor_sync(0xffffffffu, den2, off);
        den3 += __shfl_xor_sync(0xffffffffu, den3, off);
        sae0 += __shfl_xor_sync(0xffffffffu, sae0, off);
        sae1 += __shfl_xor_sync(0xffffffffu, sae1, off);
        sae2 += __shfl_xor_sync(0xffffffffu, sae2, off);
        sae3 += __shfl_xor_sync(0xffffffffu, sae3, off);
    }

    // self-loop: logit uses mean of incoming edge logits
    float invdeg = 1.f / fmaxf((float)(end - beg), 1.f);
    float exs0 = __expf(lrelu(asl.x + adv.x + sae0 * invdeg));
    float exs1 = __expf(lrelu(asl.y + adv.y + sae1 * invdeg));
    float exs2 = __expf(lrelu(asl.z + adv.z + sae2 * invdeg));
    float exs3 = __expf(lrelu(asl.w + adv.w + sae3 * invdeg));
    {
        const __half2* xr = (const __half2*)(g_xph + (size_t)n * HC) + lane;
        float2 p0 = __half22float2(xr[0]);
        float2 p1 = __half22float2(xr[32]);
        float2 p2 = __half22float2(xr[64]);
        float2 p3 = __half22float2(xr[96]);
        acc[0] += exs0 * p0.x; acc[1] += exs0 * p0.y;
        acc[2] += exs1 * p1.x; acc[3] += exs1 * p1.y;
        acc[4] += exs2 * p2.x; acc[5] += exs2 * p2.y;
        acc[6] += exs3 * p3.x; acc[7] += exs3 * p3.y;
    }
    den0 += exs0; den1 += exs1; den2 += exs2; den3 += exs3;

    float r0 = acc[0] / den0 + acc[2] / den1 + acc[4] / den2 + acc[6] / den3;
    float r1 = acc[1] / den0 + acc[3] / den1 + acc[5] / den2 + acc[7] / den3;
    float2 cb = *(const float2*)&conv_b[lane * 2];
    float v0 = fmaxf(0.25f * r0 + cb.x, 0.f);
    float v1 = fmaxf(0.25f * r1 + cb.y, 0.f);
    if (layer < 2) {
        *(__half2*)&g_hh[n * HDIM + lane * 2] = __floats2half2_rn(v0, v1);
    } else {
        int b = batch[n];
        atomicAdd(&g_pool[b * 64 + lane * 2], v0);
        atomicAdd(&g_pool[b * 64 + lane * 2 + 1], v1);
        if (lane == 0) atomicAdd(&g_cnt[b], 1);
    }
}

// ---------------- head MLP ---------------------------------------------------
__global__ __launch_bounds__(256) void final_kernel(const float* __restrict__ u,
                                                    const float* __restrict__ gW, const float* __restrict__ gb,
                                                    const float* __restrict__ f1W, const float* __restrict__ f1b,
                                                    const float* __restrict__ f2W, const float* __restrict__ f2b,
                                                    float* __restrict__ out) {
    __shared__ float pooled[NB * HDIM];
    __shared__ float ug[NB * HDIM];
    __shared__ float z1[NB * HDIM];
    int t = threadIdx.x;
    for (int i = t; i < NB * HDIM; i += 256) {
        int b = i >> 6, c = i & 63;
        float cnt = fmaxf((float)g_cnt[b], 1.f);
        pooled[i] = g_pool[i] / cnt;
        float s = gb[c];
        #pragma unroll
        for (int k = 0; k < 10; k++) s += u[b * 10 + k] * gW[k * 64 + c];
        ug[i] = fmaxf(s, 0.f);
    }
    __syncthreads();
    for (int i = t; i < NB * HDIM; i += 256) {
        int b = i >> 6, j = i & 63;
        float s = f1b[j];
        #pragma unroll 8
        for (int k = 0; k < 64; k++) s += pooled[b * 64 + k] * f1W[k * 64 + j];
        #pragma unroll 8
        for (int k = 0; k < 64; k++) s += ug[b * 64 + k] * f1W[(64 + k) * 64 + j];
        z1[i] = fmaxf(s, 0.f);
    }
    __syncthreads();
    if (t < NB * 2) {
        int b = t >> 1, o = t & 1;
        float s = f2b[o];
        #pragma unroll 8
        for (int k = 0; k < 64; k++) s += z1[b * 64 + k] * f2W[k * 2 + o];
        out[b * 2 + o] = s;
    }
}

// ---------------- launch ------------------------------------------------------
extern "C" void kernel_launch(void* const* d_in, const int* in_sizes, int n_in,
                              void* d_out, int out_size) {
    const float* x       = (const float*)d_in[0];
    const int*   eidx    = (const int*)d_in[1];
    const float* eattr   = (const float*)d_in[2];
    const float* u       = (const float*)d_in[3];
    const int*   batch   = (const int*)d_in[4];
    const float* node_W  = (const float*)d_in[5];
    const float* node_b  = (const float*)d_in[6];
    const float* eemb_W  = (const float*)d_in[7];
    const float* eemb_b  = (const float*)d_in[8];
    const float* lin_W   = (const float*)d_in[9];
    const float* att_src = (const float*)d_in[10];
    const float* att_dst = (const float*)d_in[11];
    const float* lin_eW  = (const float*)d_in[12];
    const float* att_e   = (const float*)d_in[13];
    const float* conv_b  = (const float*)d_in[14];
    const float* gW      = (const float*)d_in[15];
    const float* gb      = (const float*)d_in[16];
    const float* f1W     = (const float*)d_in[17];
    const float* f1b     = (const float*)d_in[18];
    const float* f2W     = (const float*)d_in[19];
    const float* f2b     = (const float*)d_in[20];
    float* out = (float*)d_out;

    const int* src = eidx;
    const int* dst = eidx + NE;

    void *p_deg, *p_fill;
    cudaGetSymbolAddress(&p_deg,  g_deg);
    cudaGetSymbolAddress(&p_fill, g_fill);

    cudaMemsetAsync(p_deg,  0, NN * sizeof(int));
    cudaMemsetAsync(p_fill, 0, NN * sizeof(int));

    int pre_blocks = PRE_WEATT_BLOCKS + (NN * HDIM + 255) / 256;
    pre_kernel<<<pre_blocks, 256>>>(dst, x, node_W, node_b, lin_eW, att_e, lin_W);
    scan_kernel<<<1, 1024>>>();
    edge_emb_kernel<<<(NE + 255) / 256, 256>>>(eattr, src, dst, eemb_W, eemb_b);

    for (int l = 0; l < NL; l++) {
        gemm_attn_kernel<<<NN / 32, 256>>>(l, att_src + l * NH * 64,
                                           att_dst + l * NH * 64);
        aggr_kernel<<<(NN * 32 + 255) / 256, 256>>>(conv_b + l * 64, l, batch);
    }
    final_kernel<<<1, 256>>>(u, gW, gb, f1W, f1b, f2W, f2b, out);
}

// round 15
// speedup vs baseline: 1.0416x; 1.0416x over previous
#include <cuda_runtime.h>
#include <cuda_fp16.h>
#include <cstdint>

#define NN 20000
#define NE 320000
#define NB 32
#define HDIM 64
#define HC 256   // H*C
#define NH 4
#define NL 3

// ---------------- scratch (device globals; no allocation allowed) ----------
__device__ int    g_deg[NN];
__device__ int    g_rowptr[NN + 1];
__device__ int    g_fill[NN];
__device__ int    g_csrc[NE];
__device__ __half g_hh[NN * HDIM];         // fp16 node features (layer input)
__device__ __half g_Wh[NL * HDIM * HC];    // fp16 conv weights
__device__ __half g_xph[NN * HC];          // fp16 projected features
__device__ float  g_as[NN * NH];
__device__ float  g_ad[NN * NH];
__device__ float  g_aedeP[NL * NE * 4];    // per-layer planes of edge logits, CSR order
__device__ float  g_weatt[HDIM * 12];
__device__ float  g_pool[NB * HDIM];
__device__ int    g_cnt[NB];

__device__ __forceinline__ float lrelu(float x) { return x > 0.f ? x : 0.2f * x; }

// ---------------- combined pre-kernel ---------------------------------------
#define PRE_WEATT_BLOCKS 96
__global__ __launch_bounds__(256) void pre_kernel(const int* __restrict__ dst,
                                                  const float* __restrict__ x,
                                                  const float* __restrict__ node_W,
                                                  const float* __restrict__ node_b,
                                                  const float* __restrict__ lin_eW,
                                                  const float* __restrict__ att_e,
                                                  const float* __restrict__ lin_W) {
    if (blockIdx.x < PRE_WEATT_BLOCKS) {
        int wid = (blockIdx.x * 256 + threadIdx.x) >> 5;
        int lane = threadIdx.x & 31;
        if (wid >= NL * HDIM * NH) return;
        int l = wid >> 8;
        int rem = wid & 255;
        int d = rem >> 2;
        int h = rem & 3;
        const float* w = lin_eW + l * HDIM * HC + d * HC + h * 64;
        const float* a = att_e + l * NH * 64 + h * 64;
        float s = w[lane] * a[lane] + w[32 + lane] * a[32 + lane];
        #pragma unroll
        for (int off = 16; off >= 1; off >>= 1) s += __shfl_xor_sync(0xffffffffu, s, off);
        if (lane == 0) g_weatt[d * 12 + l * 4 + h] = s;
        return;
    }
    int idx = (blockIdx.x - PRE_WEATT_BLOCKS) * 256 + threadIdx.x;
    if (idx < NE) atomicAdd(&g_deg[dst[idx]], 1);
    if (idx < NB * HDIM) g_pool[idx] = 0.f;
    if (idx < NB) g_cnt[idx] = 0;
    if (idx < NL * HDIM * HC / 2) {
        float2 wv = *(const float2*)&lin_W[idx * 2];
        *(__half2*)&g_Wh[idx * 2] = __floats2half2_rn(wv.x, wv.y);
    }
    if (idx < NN * HDIM) {
        int n = idx >> 6, c = idx & 63;
        float v = x[n * 3 + 0] * node_W[c] + x[n * 3 + 1] * node_W[64 + c]
                + x[n * 3 + 2] * node_W[128 + c] + node_b[c];
        g_hh[idx] = __float2half(fmaxf(v, 0.f));
    }
}

// ---------------- scan: single block, 20 elements per thread ---------------
__global__ __launch_bounds__(1024) void scan_kernel() {
    __shared__ int wsum[32];
    const int PER = 20;
    int t = threadIdx.x;
    int lane = t & 31, w = t >> 5;
    int v[PER];
    int sum = 0;
    int base = t * PER;
    if (t < 1000) {
        #pragma unroll
        for (int i = 0; i < PER; i++) {
            sum += g_deg[base + i];
            v[i] = sum;
        }
    }
    int x = sum;
    #pragma unroll
    for (int off = 1; off < 32; off <<= 1) {
        int y = __shfl_up_sync(0xffffffffu, x, off);
        if (lane >= off) x += y;
    }
    if (lane == 31) wsum[w] = x;
    __syncthreads();
    if (w == 0) {
        int y = wsum[lane];
        #pragma unroll
        for (int off = 1; off < 32; off <<= 1) {
            int z = __shfl_up_sync(0xffffffffu, y, off);
            if (lane >= off) y += z;
        }
        wsum[lane] = y;
    }
    __syncthreads();
    int prefix = x - sum + (w > 0 ? wsum[w - 1] : 0);
    if (t < 1000) {
        if (t == 0) g_rowptr[0] = 0;
        #pragma unroll
        for (int i = 0; i < PER; i++) g_rowptr[base + i + 1] = prefix + v[i];
    }
}

// ---- edge embedding -> 12 logits, fused CSR scatter (no atomics to aeds) ----
__global__ __launch_bounds__(256) void edge_emb_kernel(const float* __restrict__ eattr,
                                                       const int* __restrict__ src,
                                                       const int* __restrict__ dst,
                                                       const float* __restrict__ eemb_W,
                                                       const float* __restrict__ eemb_b) {
    __shared__ float4 sW4[64];
    __shared__ float  sb64[64];
    __shared__ float4 sA4[64 * 3];
    int t = threadIdx.x;
    if (t < 64) {
        sW4[t] = make_float4(eemb_W[t], eemb_W[64 + t], eemb_W[128 + t], eemb_W[192 + t]);
        sb64[t] = eemb_b[t];
    }
    for (int i = t; i < 64 * 3; i += 256) sA4[i] = ((const float4*)g_weatt)[i];
    __syncthreads();

    int e = blockIdx.x * blockDim.x + t;
    if (e >= NE) return;
    float4 a = *(const float4*)&eattr[e * 4];
    float aed[12];
    #pragma unroll
    for (int o = 0; o < 12; o++) aed[o] = 0.f;
    #pragma unroll 4
    for (int d = 0; d < 64; d++) {
        float4 w = sW4[d];
        float ea = fmaxf(a.x * w.x + a.y * w.y + a.z * w.z + a.w * w.w + sb64[d], 0.f);
        float4 A0 = sA4[d * 3 + 0], A1 = sA4[d * 3 + 1], A2 = sA4[d * 3 + 2];
        aed[0] += ea * A0.x; aed[1] += ea * A0.y; aed[2]  += ea * A0.z; aed[3]  += ea * A0.w;
        aed[4] += ea * A1.x; aed[5] += ea * A1.y; aed[6]  += ea * A1.z; aed[7]  += ea * A1.w;
        aed[8] += ea * A2.x; aed[9] += ea * A2.y; aed[10] += ea * A2.z; aed[11] += ea * A2.w;
    }
    int dn = dst[e];
    int sn = src[e];
    int p = atomicAdd(&g_fill[dn], 1);
    int slot = g_rowptr[dn] + p;
    g_csrc[slot] = sn;
    float4* P = (float4*)g_aedeP;
    P[0 * NE + slot] = make_float4(aed[0], aed[1], aed[2],  aed[3]);
    P[1 * NE + slot] = make_float4(aed[4], aed[5], aed[6],  aed[7]);
    P[2 * NE + slot] = make_float4(aed[8], aed[9], aed[10], aed[11]);
}

// ---------------- tensor-core GEMM + fused a_s/a_d (R9 geometry) ------------
// 64 rows x 256 cols per block, 16 warps; warp = (wm 0..3)+4*wn: 16 rows x 64 cols.
__device__ __forceinline__ void mma16816(float& c0, float& c1, float& c2, float& c3,
                                         uint32_t a0, uint32_t a1, uint32_t a2, uint32_t a3,
                                         uint32_t b0, uint32_t b1) {
    asm volatile(
        "mma.sync.aligned.m16n8k16.row.col.f32.f16.f16.f32 "
        "{%0,%1,%2,%3},{%4,%5,%6,%7},{%8,%9},{%0,%1,%2,%3};"
        : "+f"(c0), "+f"(c1), "+f"(c2), "+f"(c3)
        : "r"(a0), "r"(a1), "r"(a2), "r"(a3), "r"(b0), "r"(b1));
}

#define BPAD 264   // 256 + 8 halves

__global__ __launch_bounds__(512) void gemm_attn_kernel(int layer,
                                                        const float* __restrict__ att_src,
                                                        const float* __restrict__ att_dst) {
    __shared__ __half Ah[64][72];
    __shared__ __half Bh[64][BPAD];
    __shared__ float  sAs[256], sAd[256];

    int tid = threadIdx.x;
    int warp = tid >> 5, lane = tid & 31;
    int n0 = blockIdx.x * 64;

    if (tid < 256) { sAs[tid] = att_src[tid]; sAd[tid] = att_dst[tid]; }

    {
        int row = tid >> 3, cb = (tid & 7) * 8;
        uint4 v = make_uint4(0u, 0u, 0u, 0u);
        if (n0 + row < NN) v = *(const uint4*)&g_hh[(size_t)(n0 + row) * HDIM + cb];
        *(uint4*)&Ah[row][cb] = v;
    }
    {
        int kr = tid >> 3, cb = (tid & 7) * 32;
        const uint4* srcp = (const uint4*)&g_Wh[(size_t)layer * HDIM * HC + (size_t)kr * HC + cb];
        uint4* dstp = (uint4*)&Bh[kr][cb];
        dstp[0] = srcp[0];
        dstp[1] = srcp[1];
        dstp[2] = srcp[2];
        dstp[3] = srcp[3];
    }
    __syncthreads();

    int wm = warp & 3, wn = warp >> 2;        // wn = head
    int mrow = wm * 16;
    int ncol0 = wn * 64;

    uint32_t afr[4][4];
    {
        int r = mrow + (lane & 7) + ((lane >> 3) & 1) * 8;
        int kc = ((lane >> 4) & 1) * 8;
        #pragma unroll
        for (int ks = 0; ks < 4; ks++) {
            unsigned addr = (unsigned)__cvta_generic_to_shared(&Ah[r][ks * 16 + kc]);
            asm volatile("ldmatrix.sync.aligned.m8n8.x4.shared.b16 {%0,%1,%2,%3}, [%4];"
                         : "=r"(afr[ks][0]), "=r"(afr[ks][1]), "=r"(afr[ks][2]), "=r"(afr[ks][3])
                         : "r"(addr));
        }
    }

    float acc[8][4];
    #pragma unroll
    for (int nt = 0; nt < 8; nt++)
        #pragma unroll
        for (int j = 0; j < 4; j++) acc[nt][j] = 0.f;

    int bl8 = lane & 7, bm2 = (lane >> 3) & 1;
    #pragma unroll
    for (int nt = 0; nt < 8; nt++) {
        int ncol = ncol0 + nt * 8;
        #pragma unroll
        for (int ks = 0; ks < 4; ks++) {
            unsigned addr = (unsigned)__cvta_generic_to_shared(&Bh[ks * 16 + bl8 + bm2 * 8][ncol]);
            uint32_t b0, b1;
            asm volatile("ldmatrix.sync.aligned.m8n8.x2.trans.shared.b16 {%0,%1}, [%2];"
                         : "=r"(b0), "=r"(b1) : "r"(addr));
            mma16816(acc[nt][0], acc[nt][1], acc[nt][2], acc[nt][3],
                     afr[ks][0], afr[ks][1], afr[ks][2], afr[ks][3], b0, b1);
        }
    }

    // a_s/a_d from fragments (warp cols == head wn)
    {
        int c0 = ncol0 + (lane & 3) * 2;
        int row0 = mrow + (lane >> 2);
        float sp0 = 0.f, sp1 = 0.f, dp0 = 0.f, dp1 = 0.f;
        #pragma unroll
        for (int nt = 0; nt < 8; nt++) {
            float a0 = sAs[c0 + nt * 8], a1 = sAs[c0 + nt * 8 + 1];
            float d0 = sAd[c0 + nt * 8], d1 = sAd[c0 + nt * 8 + 1];
            sp0 += acc[nt][0] * a0 + acc[nt][1] * a1;
            sp1 += acc[nt][2] * a0 + acc[nt][3] * a1;
            dp0 += acc[nt][0] * d0 + acc[nt][1] * d1;
            dp1 += acc[nt][2] * d0 + acc[nt][3] * d1;
        }
        #pragma unroll
        for (int off = 1; off <= 2; off <<= 1) {
            sp0 += __shfl_xor_sync(0xffffffffu, sp0, off);
            sp1 += __shfl_xor_sync(0xffffffffu, sp1, off);
            dp0 += __shfl_xor_sync(0xffffffffu, dp0, off);
            dp1 += __shfl_xor_sync(0xffffffffu, dp1, off);
        }
        if ((lane & 3) == 0) {
            if (n0 + row0 < NN) {
                g_as[(n0 + row0) * 4 + wn] = sp0;
                g_ad[(n0 + row0) * 4 + wn] = dp0;
            }
            if (n0 + row0 + 8 < NN) {
                g_as[(n0 + row0 + 8) * 4 + wn] = sp1;
                g_ad[(n0 + row0 + 8) * 4 + wn] = dp1;
            }
        }
    }

    // direct xp stores from fragments
    {
        int r0g = n0 + mrow + (lane >> 2);
        int c0 = ncol0 + (lane & 3) * 2;
        #pragma unroll
        for (int nt = 0; nt < 8; nt++) {
            if (r0g < NN)
                *(__half2*)&g_xph[(size_t)r0g * HC + c0 + nt * 8] =
                    __floats2half2_rn(acc[nt][0], acc[nt][1]);
            if (r0g + 8 < NN)
                *(__half2*)&g_xph[(size_t)(r0g + 8) * HC + c0 + nt * 8] =
                    __floats2half2_rn(acc[nt][2], acc[nt][3]);
        }
    }
}

// ---- softmax + aggregation, 1 warp/node (R9 structure; self-logit fused) ---
__global__ __launch_bounds__(256) void aggr_kernel(const float* __restrict__ conv_b, int layer,
                                                   const int* __restrict__ batch) {
    int warp = (blockIdx.x * blockDim.x + threadIdx.x) >> 5;
    if (warp >= NN) return;
    int lane = threadIdx.x & 31;
    int n = warp;
    int beg = g_rowptr[n], end = g_rowptr[n + 1];

    float4 adv = *(const float4*)&g_ad[n * 4];
    float4 asl = *(const float4*)&g_as[n * 4];

    float den0 = 0.f, den1 = 0.f, den2 = 0.f, den3 = 0.f;
    float sae0 = 0.f, sae1 = 0.f, sae2 = 0.f, sae3 = 0.f;  // sum of edge logits
    float acc[8];
    #pragma unroll
    for (int j = 0; j < 8; j++) acc[j] = 0.f;

    const float4* plane = (const float4*)g_aedeP + (size_t)layer * NE;
    for (int base = beg; base < end; base += 32) {
        int cnt = min(32, end - base);
        float f0 = 0.f, f1 = 0.f, f2 = 0.f, f3 = 0.f;
        int ss = 0;
        if (lane < cnt) {
            int e = base + lane;
            ss = g_csrc[e];
            float4 av = *(const float4*)&g_as[ss * 4];
            float4 ae = plane[e];
            sae0 += ae.x; sae1 += ae.y; sae2 += ae.z; sae3 += ae.w;
            f0 = __expf(lrelu(av.x + adv.x + ae.x));
            f1 = __expf(lrelu(av.y + adv.y + ae.y));
            f2 = __expf(lrelu(av.z + adv.z + ae.z));
            f3 = __expf(lrelu(av.w + adv.w + ae.w));
        }
        den0 += f0; den1 += f1; den2 += f2; den3 += f3;
        #pragma unroll 2
        for (int t = 0; t < cnt; t++) {
            float b0 = __shfl_sync(0xffffffffu, f0, t);
            float b1 = __shfl_sync(0xffffffffu, f1, t);
            float b2 = __shfl_sync(0xffffffffu, f2, t);
            float b3 = __shfl_sync(0xffffffffu, f3, t);
            int sb = __shfl_sync(0xffffffffu, ss, t);
            const __half2* xr = (const __half2*)(g_xph + (size_t)sb * HC) + lane;
            float2 p0 = __half22float2(xr[0]);
            float2 p1 = __half22float2(xr[32]);
            float2 p2 = __half22float2(xr[64]);
            float2 p3 = __half22float2(xr[96]);
            acc[0] += b0 * p0.x; acc[1] += b0 * p0.y;
            acc[2] += b1 * p1.x; acc[3] += b1 * p1.y;
            acc[4] += b2 * p2.x; acc[5] += b2 * p2.y;
            acc[6] += b3 * p3.x; acc[7] += b3 * p3.y;
        }
    }
    #pragma unroll
    for (int off = 16; off >= 1; off >>= 1) {
        den0 += __shfl_xor_sync(0xffffffffu, den0, off);
        den1 += __shfl_xor_sync(0xffffffffu, den1, off);
        den2 += __shfl_xor_sync(0xffffffffu, den2, off);
        den3 += __shfl_xor_sync(0xffffffffu, den3, off);
        sae0 += __shfl_xor_sync(0xffffffffu, sae0, off);
        sae1 += __shfl_xor_sync(0xffffffffu, sae1, off);
        sae2 += __shfl_xor_sync(0xffffffffu, sae2, off);
        sae3 += __shfl_xor_sync(0xffffffffu, sae3, off);
    }

    // self-loop: logit uses mean of incoming edge logits
    float invdeg = 1.f / fmaxf((float)(end - beg), 1.f);
    float exs0 = __expf(lrelu(asl.x + adv.x + sae0 * invdeg));
    float exs1 = __expf(lrelu(asl.y + adv.y + sae1 * invdeg));
    float exs2 = __expf(lrelu(asl.z + adv.z + sae2 * invdeg));
    float exs3 = __expf(lrelu(asl.w + adv.w + sae3 * invdeg));
    {
        const __half2* xr = (const __half2*)(g_xph + (size_t)n * HC) + lane;
        float2 p0 = __half22float2(xr[0]);
        float2 p1 = __half22float2(xr[32]);
        float2 p2 = __half22float2(xr[64]);
        float2 p3 = __half22float2(xr[96]);
        acc[0] += exs0 * p0.x; acc[1] += exs0 * p0.y;
        acc[2] += exs1 * p1.x; acc[3] += exs1 * p1.y;
        acc[4] += exs2 * p2.x; acc[5] += exs2 * p2.y;
        acc[6] += exs3 * p3.x; acc[7] += exs3 * p3.y;
    }
    den0 += exs0; den1 += exs1; den2 += exs2; den3 += exs3;

    float r0 = acc[0] / den0 + acc[2] / den1 + acc[4] / den2 + acc[6] / den3;
    float r1 = acc[1] / den0 + acc[3] / den1 + acc[5] / den2 + acc[7] / den3;
    float2 cb = *(const float2*)&conv_b[lane * 2];
    float v0 = fmaxf(0.25f * r0 + cb.x, 0.f);
    float v1 = fmaxf(0.25f * r1 + cb.y, 0.f);
    if (layer < 2) {
        *(__half2*)&g_hh[n * HDIM + lane * 2] = __floats2half2_rn(v0, v1);
    } else {
        int b = batch[n];
        atomicAdd(&g_pool[b * 64 + lane * 2], v0);
        atomicAdd(&g_pool[b * 64 + lane * 2 + 1], v1);
        if (lane == 0) atomicAdd(&g_cnt[b], 1);
    }
}

// ---------------- head MLP ---------------------------------------------------
__global__ __launch_bounds__(256) void final_kernel(const float* __restrict__ u,
                                                    const float* __restrict__ gW, const float* __restrict__ gb,
                                                    const float* __restrict__ f1W, const float* __restrict__ f1b,
                                                    const float* __restrict__ f2W, const float* __restrict__ f2b,
                                                    float* __restrict__ out) {
    __shared__ float pooled[NB * HDIM];
    __shared__ float ug[NB * HDIM];
    __shared__ float z1[NB * HDIM];
    int t = threadIdx.x;
    for (int i = t; i < NB * HDIM; i += 256) {
        int b = i >> 6, c = i & 63;
        float cnt = fmaxf((float)g_cnt[b], 1.f);
        pooled[i] = g_pool[i] / cnt;
        float s = gb[c];
        #pragma unroll
        for (int k = 0; k < 10; k++) s += u[b * 10 + k] * gW[k * 64 + c];
        ug[i] = fmaxf(s, 0.f);
    }
    __syncthreads();
    for (int i = t; i < NB * HDIM; i += 256) {
        int b = i >> 6, j = i & 63;
        float s = f1b[j];
        #pragma unroll 8
        for (int k = 0; k < 64; k++) s += pooled[b * 64 + k] * f1W[k * 64 + j];
        #pragma unroll 8
        for (int k = 0; k < 64; k++) s += ug[b * 64 + k] * f1W[(64 + k) * 64 + j];
        z1[i] = fmaxf(s, 0.f);
    }
    __syncthreads();
    if (t < NB * 2) {
        int b = t >> 1, o = t & 1;
        float s = f2b[o];
        #pragma unroll 8
        for (int k = 0; k < 64; k++) s += z1[b * 64 + k] * f2W[k * 2 + o];
        out[b * 2 + o] = s;
    }
}

// ---------------- launch ------------------------------------------------------
extern "C" void kernel_launch(void* const* d_in, const int* in_sizes, int n_in,
                              void* d_out, int out_size) {
    const float* x       = (const float*)d_in[0];
    const int*   eidx    = (const int*)d_in[1];
    const float* eattr   = (const float*)d_in[2];
    const float* u       = (const float*)d_in[3];
    const int*   batch   = (const int*)d_in[4];
    const float* node_W  = (const float*)d_in[5];
    const float* node_b  = (const float*)d_in[6];
    const float* eemb_W  = (const float*)d_in[7];
    const float* eemb_b  = (const float*)d_in[8];
    const float* lin_W   = (const float*)d_in[9];
    const float* att_src = (const float*)d_in[10];
    const float* att_dst = (const float*)d_in[11];
    const float* lin_eW  = (const float*)d_in[12];
    const float* att_e   = (const float*)d_in[13];
    const float* conv_b  = (const float*)d_in[14];
    const float* gW      = (const float*)d_in[15];
    const float* gb      = (const float*)d_in[16];
    const float* f1W     = (const float*)d_in[17];
    const float* f1b     = (const float*)d_in[18];
    const float* f2W     = (const float*)d_in[19];
    const float* f2b     = (const float*)d_in[20];
    float* out = (float*)d_out;

    const int* src = eidx;
    const int* dst = eidx + NE;

    void *p_deg, *p_fill;
    cudaGetSymbolAddress(&p_deg,  g_deg);
    cudaGetSymbolAddress(&p_fill, g_fill);

    cudaMemsetAsync(p_deg,  0, NN * sizeof(int));
    cudaMemsetAsync(p_fill, 0, NN * sizeof(int));

    int pre_blocks = PRE_WEATT_BLOCKS + (NN * HDIM + 255) / 256;
    pre_kernel<<<pre_blocks, 256>>>(dst, x, node_W, node_b, lin_eW, att_e, lin_W);
    scan_kernel<<<1, 1024>>>();
    edge_emb_kernel<<<(NE + 255) / 256, 256>>>(eattr, src, dst, eemb_W, eemb_b);

    for (int l = 0; l < NL; l++) {
        gemm_attn_kernel<<<(NN + 63) / 64, 512>>>(l, att_src + l * NH * 64,
                                                  att_dst + l * NH * 64);
        aggr_kernel<<<(NN * 32 + 255) / 256, 256>>>(conv_b + l * 64, l, batch);
    }
    final_kernel<<<1, 256>>>(u, gW, gb, f1W, f1b, f2W, f2b, out);
}

// round 16
// speedup vs baseline: 1.1096x; 1.0653x over previous
#include <cuda_runtime.h>
#include <cuda_fp16.h>
#include <cstdint>

#define NN 20000
#define NE 320000
#define NB 32
#define HDIM 64
#define HC 256   // H*C
#define NH 4
#define NL 3

// ---------------- scratch (device globals; no allocation allowed) ----------
__device__ int    g_deg[NN];
__device__ int    g_rowptr[NN + 1];
__device__ int    g_fill[NN];
__device__ int    g_csrc[NE];
__device__ __half g_hh[NN * HDIM];         // fp16 node features (layer input)
__device__ __half g_Wh[NL * HDIM * HC];    // fp16 conv weights
__device__ __half g_xph[NN * HC];          // fp16 projected features
__device__ float  g_as[NN * NH];
__device__ float  g_ad[NN * NH];
__device__ float  g_aedeP[NL * NE * 4];    // per-layer planes of edge logits, CSR order
__device__ float  g_aeds[NN * 12];         // self-loop logit sums (divided by deg at read)
__device__ float  g_weatt[HDIM * 12];
__device__ float  g_pool[NB * HDIM];
__device__ int    g_cnt[NB];

__device__ __forceinline__ float lrelu(float x) { return x > 0.f ? x : 0.2f * x; }

// ---------------- zero kernel (replaces memsets) -----------------------------
__global__ __launch_bounds__(256) void zero_kernel() {
    int i = blockIdx.x * blockDim.x + threadIdx.x;
    if (i < NN) { g_deg[i] = 0; g_fill[i] = 0; }
}

// ---------------- combined pre-kernel ---------------------------------------
#define PRE_WEATT_BLOCKS 96
__global__ __launch_bounds__(256) void pre_kernel(const int* __restrict__ dst,
                                                  const float* __restrict__ x,
                                                  const float* __restrict__ node_W,
                                                  const float* __restrict__ node_b,
                                                  const float* __restrict__ lin_eW,
                                                  const float* __restrict__ att_e,
                                                  const float* __restrict__ lin_W) {
    if (blockIdx.x < PRE_WEATT_BLOCKS) {
        int wid = (blockIdx.x * 256 + threadIdx.x) >> 5;
        int lane = threadIdx.x & 31;
        if (wid >= NL * HDIM * NH) return;
        int l = wid >> 8;
        int rem = wid & 255;
        int d = rem >> 2;
        int h = rem & 3;
        const float* w = lin_eW + l * HDIM * HC + d * HC + h * 64;
        const float* a = att_e + l * NH * 64 + h * 64;
        float s = w[lane] * a[lane] + w[32 + lane] * a[32 + lane];
        #pragma unroll
        for (int off = 16; off >= 1; off >>= 1) s += __shfl_xor_sync(0xffffffffu, s, off);
        if (lane == 0) g_weatt[d * 12 + l * 4 + h] = s;
        return;
    }
    int idx = (blockIdx.x - PRE_WEATT_BLOCKS) * 256 + threadIdx.x;
    if (idx < NE) atomicAdd(&g_deg[dst[idx]], 1);
    if (idx < NN * 12) g_aeds[idx] = 0.f;
    if (idx < NB * HDIM) g_pool[idx] = 0.f;
    if (idx < NB) g_cnt[idx] = 0;
    if (idx < NL * HDIM * HC / 2) {
        float2 wv = *(const float2*)&lin_W[idx * 2];
        *(__half2*)&g_Wh[idx * 2] = __floats2half2_rn(wv.x, wv.y);
    }
    if (idx < NN * HDIM) {
        int n = idx >> 6, c = idx & 63;
        float v = x[n * 3 + 0] * node_W[c] + x[n * 3 + 1] * node_W[64 + c]
                + x[n * 3 + 2] * node_W[128 + c] + node_b[c];
        g_hh[idx] = __float2half(fmaxf(v, 0.f));
    }
}

// ---------------- scan: single block, 20 elements per thread ---------------
__global__ __launch_bounds__(1024) void scan_kernel() {
    __shared__ int wsum[32];
    const int PER = 20;
    int t = threadIdx.x;
    int lane = t & 31, w = t >> 5;
    int v[PER];
    int sum = 0;
    int base = t * PER;
    if (t < 1000) {
        #pragma unroll
        for (int i = 0; i < PER; i++) {
            sum += g_deg[base + i];
            v[i] = sum;
        }
    }
    int x = sum;
    #pragma unroll
    for (int off = 1; off < 32; off <<= 1) {
        int y = __shfl_up_sync(0xffffffffu, x, off);
        if (lane >= off) x += y;
    }
    if (lane == 31) wsum[w] = x;
    __syncthreads();
    if (w == 0) {
        int y = wsum[lane];
        #pragma unroll
        for (int off = 1; off < 32; off <<= 1) {
            int z = __shfl_up_sync(0xffffffffu, y, off);
            if (lane >= off) y += z;
        }
        wsum[lane] = y;
    }
    __syncthreads();
    int prefix = x - sum + (w > 0 ? wsum[w - 1] : 0);
    if (t < 1000) {
        if (t == 0) g_rowptr[0] = 0;
        #pragma unroll
        for (int i = 0; i < PER; i++) g_rowptr[base + i + 1] = prefix + v[i];
    }
}

// ---- edge embedding -> 12 logits, fused CSR scatter (claims its own slot) ----
__global__ __launch_bounds__(256) void edge_emb_kernel(const float* __restrict__ eattr,
                                                       const int* __restrict__ src,
                                                       const int* __restrict__ dst,
                                                       const float* __restrict__ eemb_W,
                                                       const float* __restrict__ eemb_b) {
    __shared__ float4 sW4[64];
    __shared__ float  sb64[64];
    __shared__ float4 sA4[64 * 3];
    int t = threadIdx.x;
    if (t < 64) {
        sW4[t] = make_float4(eemb_W[t], eemb_W[64 + t], eemb_W[128 + t], eemb_W[192 + t]);
        sb64[t] = eemb_b[t];
    }
    for (int i = t; i < 64 * 3; i += 256) sA4[i] = ((const float4*)g_weatt)[i];
    __syncthreads();

    int e = blockIdx.x * blockDim.x + t;
    if (e >= NE) return;
    float4 a = *(const float4*)&eattr[e * 4];
    float aed[12];
    #pragma unroll
    for (int o = 0; o < 12; o++) aed[o] = 0.f;
    #pragma unroll 4
    for (int d = 0; d < 64; d++) {
        float4 w = sW4[d];
        float ea = fmaxf(a.x * w.x + a.y * w.y + a.z * w.z + a.w * w.w + sb64[d], 0.f);
        float4 A0 = sA4[d * 3 + 0], A1 = sA4[d * 3 + 1], A2 = sA4[d * 3 + 2];
        aed[0] += ea * A0.x; aed[1] += ea * A0.y; aed[2]  += ea * A0.z; aed[3]  += ea * A0.w;
        aed[4] += ea * A1.x; aed[5] += ea * A1.y; aed[6]  += ea * A1.z; aed[7]  += ea * A1.w;
        aed[8] += ea * A2.x; aed[9] += ea * A2.y; aed[10] += ea * A2.z; aed[11] += ea * A2.w;
    }
    int dn = dst[e];
    int sn = src[e];
    int p = atomicAdd(&g_fill[dn], 1);
    int slot = g_rowptr[dn] + p;
    g_csrc[slot] = sn;
    float4* P = (float4*)g_aedeP;
    P[0 * NE + slot] = make_float4(aed[0], aed[1], aed[2],  aed[3]);
    P[1 * NE + slot] = make_float4(aed[4], aed[5], aed[6],  aed[7]);
    P[2 * NE + slot] = make_float4(aed[8], aed[9], aed[10], aed[11]);
    #pragma unroll
    for (int o = 0; o < 12; o++) atomicAdd(&g_aeds[dn * 12 + o], aed[o]);
}

// ---------------- tensor-core GEMM + fused a_s/a_d (R9 geometry) ------------
__device__ __forceinline__ void mma16816(float& c0, float& c1, float& c2, float& c3,
                                         uint32_t a0, uint32_t a1, uint32_t a2, uint32_t a3,
                                         uint32_t b0, uint32_t b1) {
    asm volatile(
        "mma.sync.aligned.m16n8k16.row.col.f32.f16.f16.f32 "
        "{%0,%1,%2,%3},{%4,%5,%6,%7},{%8,%9},{%0,%1,%2,%3};"
        : "+f"(c0), "+f"(c1), "+f"(c2), "+f"(c3)
        : "r"(a0), "r"(a1), "r"(a2), "r"(a3), "r"(b0), "r"(b1));
}

#define BPAD 264   // 256 + 8 halves

__global__ __launch_bounds__(512) void gemm_attn_kernel(int layer,
                                                        const float* __restrict__ att_src,
                                                        const float* __restrict__ att_dst) {
    __shared__ __half Ah[64][72];
    __shared__ __half Bh[64][BPAD];
    __shared__ float  sAs[256], sAd[256];

    int tid = threadIdx.x;
    int warp = tid >> 5, lane = tid & 31;
    int n0 = blockIdx.x * 64;

    if (tid < 256) { sAs[tid] = att_src[tid]; sAd[tid] = att_dst[tid]; }

    {
        int row = tid >> 3, cb = (tid & 7) * 8;
        uint4 v = make_uint4(0u, 0u, 0u, 0u);
        if (n0 + row < NN) v = *(const uint4*)&g_hh[(size_t)(n0 + row) * HDIM + cb];
        *(uint4*)&Ah[row][cb] = v;
    }
    {
        int kr = tid >> 3, cb = (tid & 7) * 32;
        const uint4* srcp = (const uint4*)&g_Wh[(size_t)layer * HDIM * HC + (size_t)kr * HC + cb];
        uint4* dstp = (uint4*)&Bh[kr][cb];
        dstp[0] = srcp[0];
        dstp[1] = srcp[1];
        dstp[2] = srcp[2];
        dstp[3] = srcp[3];
    }
    __syncthreads();

    int wm = warp & 3, wn = warp >> 2;        // wn = head
    int mrow = wm * 16;
    int ncol0 = wn * 64;

    uint32_t afr[4][4];
    {
        int r = mrow + (lane & 7) + ((lane >> 3) & 1) * 8;
        int kc = ((lane >> 4) & 1) * 8;
        #pragma unroll
        for (int ks = 0; ks < 4; ks++) {
            unsigned addr = (unsigned)__cvta_generic_to_shared(&Ah[r][ks * 16 + kc]);
            asm volatile("ldmatrix.sync.aligned.m8n8.x4.shared.b16 {%0,%1,%2,%3}, [%4];"
                         : "=r"(afr[ks][0]), "=r"(afr[ks][1]), "=r"(afr[ks][2]), "=r"(afr[ks][3])
                         : "r"(addr));
        }
    }

    float acc[8][4];
    #pragma unroll
    for (int nt = 0; nt < 8; nt++)
        #pragma unroll
        for (int j = 0; j < 4; j++) acc[nt][j] = 0.f;

    int bl8 = lane & 7, bm2 = (lane >> 3) & 1;
    #pragma unroll
    for (int nt = 0; nt < 8; nt++) {
        int ncol = ncol0 + nt * 8;
        #pragma unroll
        for (int ks = 0; ks < 4; ks++) {
            unsigned addr = (unsigned)__cvta_generic_to_shared(&Bh[ks * 16 + bl8 + bm2 * 8][ncol]);
            uint32_t b0, b1;
            asm volatile("ldmatrix.sync.aligned.m8n8.x2.trans.shared.b16 {%0,%1}, [%2];"
                         : "=r"(b0), "=r"(b1) : "r"(addr));
            mma16816(acc[nt][0], acc[nt][1], acc[nt][2], acc[nt][3],
                     afr[ks][0], afr[ks][1], afr[ks][2], afr[ks][3], b0, b1);
        }
    }

    // a_s/a_d from fragments (warp cols == head wn)
    {
        int c0 = ncol0 + (lane & 3) * 2;
        int row0 = mrow + (lane >> 2);
        float sp0 = 0.f, sp1 = 0.f, dp0 = 0.f, dp1 = 0.f;
        #pragma unroll
        for (int nt = 0; nt < 8; nt++) {
            float a0 = sAs[c0 + nt * 8], a1 = sAs[c0 + nt * 8 + 1];
            float d0 = sAd[c0 + nt * 8], d1 = sAd[c0 + nt * 8 + 1];
            sp0 += acc[nt][0] * a0 + acc[nt][1] * a1;
            sp1 += acc[nt][2] * a0 + acc[nt][3] * a1;
            dp0 += acc[nt][0] * d0 + acc[nt][1] * d1;
            dp1 += acc[nt][2] * d0 + acc[nt][3] * d1;
        }
        #pragma unroll
        for (int off = 1; off <= 2; off <<= 1) {
            sp0 += __shfl_xor_sync(0xffffffffu, sp0, off);
            sp1 += __shfl_xor_sync(0xffffffffu, sp1, off);
            dp0 += __shfl_xor_sync(0xffffffffu, dp0, off);
            dp1 += __shfl_xor_sync(0xffffffffu, dp1, off);
        }
        if ((lane & 3) == 0) {
            if (n0 + row0 < NN) {
                g_as[(n0 + row0) * 4 + wn] = sp0;
                g_ad[(n0 + row0) * 4 + wn] = dp0;
            }
            if (n0 + row0 + 8 < NN) {
                g_as[(n0 + row0 + 8) * 4 + wn] = sp1;
                g_ad[(n0 + row0 + 8) * 4 + wn] = dp1;
            }
        }
    }

    // direct xp stores from fragments
    {
        int r0g = n0 + mrow + (lane >> 2);
        int c0 = ncol0 + (lane & 3) * 2;
        #pragma unroll
        for (int nt = 0; nt < 8; nt++) {
            if (r0g < NN)
                *(__half2*)&g_xph[(size_t)r0g * HC + c0 + nt * 8] =
                    __floats2half2_rn(acc[nt][0], acc[nt][1]);
            if (r0g + 8 < NN)
                *(__half2*)&g_xph[(size_t)(r0g + 8) * HC + c0 + nt * 8] =
                    __floats2half2_rn(acc[nt][2], acc[nt][3]);
        }
    }
}

// ---- softmax + aggregation, 1 warp/node (R9 structure) ---------------------
__global__ __launch_bounds__(256) void aggr_kernel(const float* __restrict__ conv_b, int layer,
                                                   const int* __restrict__ batch) {
    int warp = (blockIdx.x * blockDim.x + threadIdx.x) >> 5;
    if (warp >= NN) return;
    int lane = threadIdx.x & 31;
    int n = warp;
    int beg = g_rowptr[n], end = g_rowptr[n + 1];

    float4 adv = *(const float4*)&g_ad[n * 4];
    float4 asl = *(const float4*)&g_as[n * 4];
    float4 aes = *(const float4*)&g_aeds[n * 12 + layer * 4];
    float invdeg = 1.f / fmaxf((float)(end - beg), 1.f);

    float exs0 = __expf(lrelu(asl.x + adv.x + aes.x * invdeg));
    float exs1 = __expf(lrelu(asl.y + adv.y + aes.y * invdeg));
    float exs2 = __expf(lrelu(asl.z + adv.z + aes.z * invdeg));
    float exs3 = __expf(lrelu(asl.w + adv.w + aes.w * invdeg));

    float den0 = 0.f, den1 = 0.f, den2 = 0.f, den3 = 0.f;
    float acc[8];
    {
        const __half2* xr = (const __half2*)(g_xph + (size_t)n * HC) + lane;
        float2 p0 = __half22float2(xr[0]);
        float2 p1 = __half22float2(xr[32]);
        float2 p2 = __half22float2(xr[64]);
        float2 p3 = __half22float2(xr[96]);
        acc[0] = exs0 * p0.x; acc[1] = exs0 * p0.y;
        acc[2] = exs1 * p1.x; acc[3] = exs1 * p1.y;
        acc[4] = exs2 * p2.x; acc[5] = exs2 * p2.y;
        acc[6] = exs3 * p3.x; acc[7] = exs3 * p3.y;
    }

    const float4* plane = (const float4*)g_aedeP + (size_t)layer * NE;
    for (int base = beg; base < end; base += 32) {
        int cnt = min(32, end - base);
        float f0 = 0.f, f1 = 0.f, f2 = 0.f, f3 = 0.f;
        int ss = 0;
        if (lane < cnt) {
            int e = base + lane;
            ss = g_csrc[e];
            float4 av = *(const float4*)&g_as[ss * 4];
            float4 ae = plane[e];
            f0 = __expf(lrelu(av.x + adv.x + ae.x));
            f1 = __expf(lrelu(av.y + adv.y + ae.y));
            f2 = __expf(lrelu(av.z + adv.z + ae.z));
            f3 = __expf(lrelu(av.w + adv.w + ae.w));
        }
        den0 += f0; den1 += f1; den2 += f2; den3 += f3;
        #pragma unroll 2
        for (int t = 0; t < cnt; t++) {
            float b0 = __shfl_sync(0xffffffffu, f0, t);
            float b1 = __shfl_sync(0xffffffffu, f1, t);
            float b2 = __shfl_sync(0xffffffffu, f2, t);
            float b3 = __shfl_sync(0xffffffffu, f3, t);
            int sb = __shfl_sync(0xffffffffu, ss, t);
            const __half2* xr = (const __half2*)(g_xph + (size_t)sb * HC) + lane;
            float2 p0 = __half22float2(xr[0]);
            float2 p1 = __half22float2(xr[32]);
            float2 p2 = __half22float2(xr[64]);
            float2 p3 = __half22float2(xr[96]);
            acc[0] += b0 * p0.x; acc[1] += b0 * p0.y;
            acc[2] += b1 * p1.x; acc[3] += b1 * p1.y;
            acc[4] += b2 * p2.x; acc[5] += b2 * p2.y;
            acc[6] += b3 * p3.x; acc[7] += b3 * p3.y;
        }
    }
    #pragma unroll
    for (int off = 16; off >= 1; off >>= 1) {
        den0 += __shfl_xor_sync(0xffffffffu, den0, off);
        den1 += __shfl_xor_sync(0xffffffffu, den1, off);
        den2 += __shfl_xor_sync(0xffffffffu, den2, off);
        den3 += __shfl_xor_sync(0xffffffffu, den3, off);
    }
    den0 += exs0; den1 += exs1; den2 += exs2; den3 += exs3;

    float r0 = acc[0] / den0 + acc[2] / den1 + acc[4] / den2 + acc[6] / den3;
    float r1 = acc[1] / den0 + acc[3] / den1 + acc[5] / den2 + acc[7] / den3;
    float2 cb = *(const float2*)&conv_b[lane * 2];
    float v0 = fmaxf(0.25f * r0 + cb.x, 0.f);
    float v1 = fmaxf(0.25f * r1 + cb.y, 0.f);
    if (layer < 2) {
        *(__half2*)&g_hh[n * HDIM + lane * 2] = __floats2half2_rn(v0, v1);
    } else {
        int b = batch[n];
        atomicAdd(&g_pool[b * 64 + lane * 2], v0);
        atomicAdd(&g_pool[b * 64 + lane * 2 + 1], v1);
        if (lane == 0) atomicAdd(&g_cnt[b], 1);
    }
}

// ---------------- head MLP ---------------------------------------------------
__global__ __launch_bounds__(256) void final_kernel(const float* __restrict__ u,
                                                    const float* __restrict__ gW, const float* __restrict__ gb,
                                                    const float* __restrict__ f1W, const float* __restrict__ f1b,
                                                    const float* __restrict__ f2W, const float* __restrict__ f2b,
                                                    float* __restrict__ out) {
    __shared__ float pooled[NB * HDIM];
    __shared__ float ug[NB * HDIM];
    __shared__ float z1[NB * HDIM];
    int t = threadIdx.x;
    for (int i = t; i < NB * HDIM; i += 256) {
        int b = i >> 6, c = i & 63;
        float cnt = fmaxf((float)g_cnt[b], 1.f);
        pooled[i] = g_pool[i] / cnt;
        float s = gb[c];
        #pragma unroll
        for (int k = 0; k < 10; k++) s += u[b * 10 + k] * gW[k * 64 + c];
        ug[i] = fmaxf(s, 0.f);
    }
    __syncthreads();
    for (int i = t; i < NB * HDIM; i += 256) {
        int b = i >> 6, j = i & 63;
        float s = f1b[j];
        #pragma unroll 8
        for (int k = 0; k < 64; k++) s += pooled[b * 64 + k] * f1W[k * 64 + j];
        #pragma unroll 8
        for (int k = 0; k < 64; k++) s += ug[b * 64 + k] * f1W[(64 + k) * 64 + j];
        z1[i] = fmaxf(s, 0.f);
    }
    __syncthreads();
    if (t < NB * 2) {
        int b = t >> 1, o = t & 1;
        float s = f2b[o];
        #pragma unroll 8
        for (int k = 0; k < 64; k++) s += z1[b * 64 + k] * f2W[k * 2 + o];
        out[b * 2 + o] = s;
    }
}

// ---------------- launch ------------------------------------------------------
extern "C" void kernel_launch(void* const* d_in, const int* in_sizes, int n_in,
                              void* d_out, int out_size) {
    const float* x       = (const float*)d_in[0];
    const int*   eidx    = (const int*)d_in[1];
    const float* eattr   = (const float*)d_in[2];
    const float* u       = (const float*)d_in[3];
    const int*   batch   = (const int*)d_in[4];
    const float* node_W  = (const float*)d_in[5];
    const float* node_b  = (const float*)d_in[6];
    const float* eemb_W  = (const float*)d_in[7];
    const float* eemb_b  = (const float*)d_in[8];
    const float* lin_W   = (const float*)d_in[9];
    const float* att_src = (const float*)d_in[10];
    const float* att_dst = (const float*)d_in[11];
    const float* lin_eW  = (const float*)d_in[12];
    const float* att_e   = (const float*)d_in[13];
    const float* conv_b  = (const float*)d_in[14];
    const float* gW      = (const float*)d_in[15];
    const float* gb      = (const float*)d_in[16];
    const float* f1W     = (const float*)d_in[17];
    const float* f1b     = (const float*)d_in[18];
    const float* f2W     = (const float*)d_in[19];
    const float* f2b     = (const float*)d_in[20];
    float* out = (float*)d_out;

    const int* src = eidx;
    const int* dst = eidx + NE;

    // fork stream + events (host objects only; created per call, not freed
    // mid-capture; kernel_launch is invoked only a handful of times)
    cudaStream_t s2;
    cudaStreamCreateWithFlags(&s2, cudaStreamNonBlocking);
    cudaEvent_t evA, evB;
    cudaEventCreateWithFlags(&evA, cudaEventDisableTiming);
    cudaEventCreateWithFlags(&evB, cudaEventDisableTiming);

    zero_kernel<<<(NN + 255) / 256, 256>>>();
    int pre_blocks = PRE_WEATT_BLOCKS + (NN * HDIM + 255) / 256;
    pre_kernel<<<pre_blocks, 256>>>(dst, x, node_W, node_b, lin_eW, att_e, lin_W);
    cudaEventRecord(evA, 0);

    // branch: CSR build + edge logits on s2, concurrent with gemm layer 0
    cudaStreamWaitEvent(s2, evA, 0);
    scan_kernel<<<1, 1024, 0, s2>>>();
    edge_emb_kernel<<<(NE + 255) / 256, 256, 0, s2>>>(eattr, src, dst, eemb_W, eemb_b);
    cudaEventRecord(evB, s2);

    // main: layer-0 projection (depends only on pre)
    gemm_attn_kernel<<<(NN + 63) / 64, 512>>>(0, att_src, att_dst);
    cudaStreamWaitEvent(0, evB, 0);   // aggr needs edge logits + CSR

    aggr_kernel<<<(NN * 32 + 255) / 256, 256>>>(conv_b, 0, batch);
    for (int l = 1; l < NL; l++) {
        gemm_attn_kernel<<<(NN + 63) / 64, 512>>>(l, att_src + l * NH * 64,
                                                  att_dst + l * NH * 64);
        aggr_kernel<<<(NN * 32 + 255) / 256, 256>>>(conv_b + l * 64, l, batch);
    }
    final_kernel<<<1, 256>>>(u, gW, gb, f1W, f1b, f2W, f2b, out);
}